// round 8
// baseline (speedup 1.0000x reference)
#include <cuda_runtime.h>

// Flow-warp bilinear, direct gather, y-paired pixels, row taps merged into
// LDG.128 (float4 at x0&~3) + predicated straddle load, taps extracted via selects.
// out[b,c,y,x] = bilerp(src[b,c], clamp(y+flow[b,0,y,x]), clamp(x+flow[b,1,y,x]))
// B=8, C=16, H=W=512.

#define B_ 8
#define C_ 16
#define H_ 512
#define W_ 512
#define HW_ (H_ * W_)
#define CHW_ (C_ * HW_)

// Extract v0 = A[t], v1 = (t<3) ? A[t+1] : ext   (t in 0..3), branch-free.
__device__ __forceinline__ void pick2(float4 A, float ext, bool t1, bool t2,
                                      float& v0, float& v1)
{
    float a01 = t1 ? A.y : A.x;
    float a23 = t1 ? A.w : A.z;
    v0 = t2 ? a23 : a01;
    float b01 = t1 ? A.z : A.y;
    float b23 = t1 ? ext : A.w;
    v1 = t2 ? b23 : b01;
}

__global__ void __launch_bounds__(256) warp_gather_v128_kernel(
    const float* __restrict__ src,
    const float* __restrict__ flow,
    float* __restrict__ out)
{
    int idx = blockIdx.x * blockDim.x + threadIdx.x;   // over B * H/2 * W
    int x   = idx & (W_ - 1);
    int ry  = (idx >> 9) & 255;
    int b   = idx >> 17;
    int y   = ry * 2;

    const float* __restrict__ fby = flow + b * 2 * HW_;
    const float* __restrict__ fbx = fby + HW_;

    int   gE[2];        // y0*512 + (x0 & ~3)
    bool  t1v[2], t2v[2], t3v[2];
    float wxv[2], wyv[2];

#pragma unroll
    for (int k = 0; k < 2; ++k) {
        int yy = y + k;
        int fo = yy * W_ + x;
        float fy = __ldg(fby + fo);
        float fx = __ldg(fbx + fo);
        // reference's normalize->unnormalize cancels exactly
        float py = fminf(fmaxf((float)yy + fy, 0.0f), (float)(H_ - 1));
        float px = fminf(fmaxf((float)x  + fx, 0.0f), (float)(W_ - 1));
        float y0f = floorf(py);
        float x0f = floorf(px);
        int y0 = min((int)y0f, H_ - 2);   // edge: weight becomes exactly 1
        int x0 = min((int)x0f, W_ - 2);
        wyv[k] = py - (float)y0;
        wxv[k] = px - (float)x0;
        int t = x0 & 3;
        t1v[k] = t & 1;
        t2v[k] = (t & 2) != 0;
        t3v[k] = (t == 3);
        gE[k] = (y0 << 9) + (x0 & ~3);
    }

    const float* __restrict__ sb = src + b * CHW_;
    float* __restrict__ ob = out + b * CHW_ + y * W_ + x;

    const int gA = gE[0];
    const int gB = gE[1];

#pragma unroll
    for (int c = 0; c < C_; ++c) {
        const float* __restrict__ sc = sb + c * HW_;

        // pixel A: rows y0, y0+1 as float4 + straddle scalar
        const float* pA = sc + gA;
        float4 A0 = *(const float4*)(pA);
        float4 A1 = *(const float4*)(pA + W_);
        float eA0 = t3v[0] ? __ldg(pA + 4)      : 0.0f;
        float eA1 = t3v[0] ? __ldg(pA + W_ + 4) : 0.0f;

        // pixel B
        const float* pB = sc + gB;
        float4 B0 = *(const float4*)(pB);
        float4 B1 = *(const float4*)(pB + W_);
        float eB0 = t3v[1] ? __ldg(pB + 4)      : 0.0f;
        float eB1 = t3v[1] ? __ldg(pB + W_ + 4) : 0.0f;

        float a00, a01, a10, a11, b00, b01, b10, b11;
        pick2(A0, eA0, t1v[0], t2v[0], a00, a01);
        pick2(A1, eA1, t1v[0], t2v[0], a10, a11);
        pick2(B0, eB0, t1v[1], t2v[1], b00, b01);
        pick2(B1, eB1, t1v[1], t2v[1], b10, b11);

        float atop = fmaf(wxv[0], a01 - a00, a00);
        float abot = fmaf(wxv[0], a11 - a10, a10);
        float btop = fmaf(wxv[1], b01 - b00, b00);
        float bbot = fmaf(wxv[1], b11 - b10, b10);

        float* __restrict__ oc = ob + c * HW_;
        oc[0]  = fmaf(wyv[0], abot - atop, atop);
        oc[W_] = fmaf(wyv[1], bbot - btop, btop);
    }
}

extern "C" void kernel_launch(void* const* d_in, const int* in_sizes, int n_in,
                              void* d_out, int out_size)
{
    const float* src  = (const float*)d_in[0];
    const float* flow = (const float*)d_in[1];
    float* out        = (float*)d_out;

    const int total = B_ * (H_ / 2) * W_;   // 1,048,576 threads
    warp_gather_v128_kernel<<<total / 256, 256>>>(src, flow, out);
}

// round 9
// speedup vs baseline: 1.6182x; 1.6182x over previous
#include <cuda_runtime.h>

// Flow-warp bilinear, direct scalar gather, 4 output rows per thread (max MLP),
// streaming hints for single-touch flow/out so src keeps the caches.
// out[b,c,y,x] = bilerp(src[b,c], clamp(y+flow[b,0,y,x]), clamp(x+flow[b,1,y,x]))
// B=8, C=16, H=W=512.
// Edge trick: clamp x0,y0 <= 510; when floor==511 the fractional weight is
// exactly 1.0 so the result is identical and +1 taps stay in bounds.

#define B_ 8
#define C_ 16
#define H_ 512
#define W_ 512
#define HW_ (H_ * W_)
#define CHW_ (C_ * HW_)
#define RPT_ 4   // rows per thread

__global__ void __launch_bounds__(256) warp_gather4_kernel(
    const float* __restrict__ src,
    const float* __restrict__ flow,
    float* __restrict__ out)
{
    int idx = blockIdx.x * blockDim.x + threadIdx.x;   // over B * H/4 * W
    int x   = idx & (W_ - 1);
    int ry  = (idx >> 9) & 127;
    int b   = idx >> 16;
    int y   = ry * RPT_;

    const float* __restrict__ fby = flow + b * 2 * HW_;
    const float* __restrict__ fbx = fby + HW_;

    int   g00[RPT_];
    float wxv[RPT_], wyv[RPT_];

#pragma unroll
    for (int k = 0; k < RPT_; ++k) {
        int yy = y + k;
        int fo = yy * W_ + x;
        float fy = __ldcs(fby + fo);
        float fx = __ldcs(fbx + fo);
        // reference's normalize->unnormalize cancels exactly
        float py = fminf(fmaxf((float)yy + fy, 0.0f), (float)(H_ - 1));
        float px = fminf(fmaxf((float)x  + fx, 0.0f), (float)(W_ - 1));
        float y0f = floorf(py);
        float x0f = floorf(px);
        int y0 = min((int)y0f, H_ - 2);
        int x0 = min((int)x0f, W_ - 2);
        wyv[k] = py - (float)y0;
        wxv[k] = px - (float)x0;
        g00[k] = (y0 << 9) + x0;
    }

    const float* __restrict__ sb = src + b * CHW_;
    float* __restrict__ ob = out + b * CHW_ + y * W_ + x;

#pragma unroll
    for (int c = 0; c < C_; ++c) {
        const float* __restrict__ sc = sb + c * HW_;
        float v00[RPT_], v01[RPT_], v10[RPT_], v11[RPT_];
#pragma unroll
        for (int k = 0; k < RPT_; ++k) {
            const float* p = sc + g00[k];
            v00[k] = __ldg(p);
            v01[k] = __ldg(p + 1);
            v10[k] = __ldg(p + W_);
            v11[k] = __ldg(p + W_ + 1);
        }
        float* __restrict__ oc = ob + c * HW_;
#pragma unroll
        for (int k = 0; k < RPT_; ++k) {
            float top = fmaf(wxv[k], v01[k] - v00[k], v00[k]);
            float bot = fmaf(wxv[k], v11[k] - v10[k], v10[k]);
            __stcs(oc + k * W_, fmaf(wyv[k], bot - top, top));
        }
    }
}

extern "C" void kernel_launch(void* const* d_in, const int* in_sizes, int n_in,
                              void* d_out, int out_size)
{
    const float* src  = (const float*)d_in[0];
    const float* flow = (const float*)d_in[1];
    float* out        = (float*)d_out;

    const int total = B_ * (H_ / RPT_) * W_;   // 524,288 threads
    warp_gather4_kernel<<<total / 256, 256>>>(src, flow, out);
}